// round 1
// baseline (speedup 1.0000x reference)
#include <cuda_runtime.h>
#include <cuda_bf16.h>
#include <math.h>

#define BN_EPS 1e-3f
#define SLOPE  0.1f
#define CT     30.0f

// ---------------- scratch (device globals; no allocation allowed) ----------------
__device__ float g_h1[256 * 128 * 32 * 32];   // conv1 out  (134 MB)
__device__ float g_h2[256 * 256 * 16 * 16];   // conv2 out  (67 MB)
__device__ float g_data[256 * 4096];          // embeds (normalized in place)
__device__ float g_muA[16 * 4096];
__device__ float g_muB[16 * 4096];
__device__ float g_r[256 * 16];

// =====================================================================
// conv1: x[256,3,64,64] -> h1[256,128,32,32], stride2 pad1, BN+LReLU
// grid(256, 8) : 8 oc-tiles of 16.  block 256: each thread 4 spatial x 16 oc.
// dynamic smem: input image 3*64*64 + weights 16*27 + bn (16+16)
// =====================================================================
__global__ __launch_bounds__(256) void conv1_kernel(
    const float* __restrict__ x, const float* __restrict__ w,
    const float* __restrict__ bias, const float* __restrict__ g,
    const float* __restrict__ beta, const float* __restrict__ m,
    const float* __restrict__ v, float* __restrict__ out)
{
    extern __shared__ float sm[];
    float* in_s = sm;             // 12288
    float* w_s  = sm + 12288;     // 432
    float* sc_s = w_s + 432;      // 16
    float* sh_s = sc_s + 16;      // 16

    int img = blockIdx.x;
    int oc0 = blockIdx.y * 16;
    int tid = threadIdx.x;

    const float* xin = x + img * 12288;
    for (int i = tid; i < 12288; i += 256) in_s[i] = xin[i];
    for (int i = tid; i < 16 * 27; i += 256) w_s[i] = w[oc0 * 27 + i];
    if (tid < 16) {
        int oc = oc0 + tid;
        float sc = g[oc] / sqrtf(v[oc] + BN_EPS);
        sc_s[tid] = sc;
        sh_s[tid] = beta[oc] - m[oc] * sc + bias[oc] * sc;
    }
    __syncthreads();

    int oh[4], ow[4];
#pragma unroll
    for (int i = 0; i < 4; i++) {
        int p = tid + i * 256;
        oh[i] = p >> 5;
        ow[i] = p & 31;
    }
    float acc[4][16];
#pragma unroll
    for (int i = 0; i < 4; i++)
#pragma unroll
        for (int j = 0; j < 16; j++) acc[i][j] = 0.f;

#pragma unroll
    for (int c = 0; c < 3; c++)
#pragma unroll
        for (int kh = 0; kh < 3; kh++)
#pragma unroll
            for (int kw = 0; kw < 3; kw++) {
                float wv[16];
#pragma unroll
                for (int j = 0; j < 16; j++) wv[j] = w_s[j * 27 + c * 9 + kh * 3 + kw];
#pragma unroll
                for (int i = 0; i < 4; i++) {
                    int ih = 2 * oh[i] - 1 + kh;
                    int iw = 2 * ow[i] - 1 + kw;
                    float vv = (ih >= 0 && ih < 64 && iw >= 0 && iw < 64)
                                   ? in_s[c * 4096 + ih * 64 + iw] : 0.f;
#pragma unroll
                    for (int j = 0; j < 16; j++) acc[i][j] = fmaf(vv, wv[j], acc[i][j]);
                }
            }

#pragma unroll
    for (int j = 0; j < 16; j++) {
        float sc = sc_s[j], sh = sh_s[j];
        int oc = oc0 + j;
#pragma unroll
        for (int i = 0; i < 4; i++) {
            float y = acc[i][j] * sc + sh;
            y = y > 0.f ? y : SLOPE * y;
            out[((img * 128 + oc) * 32 + oh[i]) * 32 + ow[i]] = y;
        }
    }
}

// =====================================================================
// conv2: h1[256,128,32,32] -> h2[256,256,16,16]
// grid(256, 4): 4 oc-tiles of 64. block 256 = 64 spatial-groups x 4 oc-groups.
// thread: 4 spatial x 16 oc = 64 acc. ic chunks of 8.
// dynamic smem: in 8*32*32 + w 64*8*9 = 12800 floats
// =====================================================================
__global__ __launch_bounds__(256) void conv2_kernel(
    const float* __restrict__ in, const float* __restrict__ w,
    const float* __restrict__ bias, const float* __restrict__ g,
    const float* __restrict__ beta, const float* __restrict__ m,
    const float* __restrict__ v, float* __restrict__ out)
{
    extern __shared__ float sm[];
    float* in_s = sm;           // 8192
    float* w_s  = sm + 8192;    // 4608

    int img = blockIdx.x;
    int oc0 = blockIdx.y * 64;
    int tid = threadIdx.x;
    int sg = tid & 63, og = tid >> 6;

    int oh[4], ow[4];
#pragma unroll
    for (int i = 0; i < 4; i++) {
        int p = sg + 64 * i;
        oh[i] = p >> 4;
        ow[i] = p & 15;
    }
    float acc[4][16];
#pragma unroll
    for (int i = 0; i < 4; i++)
#pragma unroll
        for (int j = 0; j < 16; j++) acc[i][j] = 0.f;

    for (int icb = 0; icb < 128; icb += 8) {
        __syncthreads();
        const float* ip = in + (img * 128 + icb) * 1024;
        for (int i = tid; i < 8192; i += 256) in_s[i] = ip[i];
        for (int i = tid; i < 4608; i += 256) {
            int ocl = i / 72, rem = i % 72;
            w_s[i] = w[(oc0 + ocl) * 1152 + icb * 9 + rem];
        }
        __syncthreads();

#pragma unroll
        for (int ic = 0; ic < 8; ic++)
#pragma unroll
            for (int kh = 0; kh < 3; kh++)
#pragma unroll
                for (int kw = 0; kw < 3; kw++) {
                    float wv[16];
#pragma unroll
                    for (int j = 0; j < 16; j++)
                        wv[j] = w_s[(og * 16 + j) * 72 + ic * 9 + kh * 3 + kw];
#pragma unroll
                    for (int i = 0; i < 4; i++) {
                        int ih = 2 * oh[i] - 1 + kh;
                        int iw = 2 * ow[i] - 1 + kw;
                        float vv = (ih >= 0 && ih < 32 && iw >= 0 && iw < 32)
                                       ? in_s[ic * 1024 + ih * 32 + iw] : 0.f;
#pragma unroll
                        for (int j = 0; j < 16; j++) acc[i][j] = fmaf(vv, wv[j], acc[i][j]);
                    }
                }
    }

#pragma unroll
    for (int j = 0; j < 16; j++) {
        int oc = oc0 + og * 16 + j;
        float sc = g[oc] / sqrtf(v[oc] + BN_EPS);
        float sh = beta[oc] - m[oc] * sc + bias[oc] * sc;
#pragma unroll
        for (int i = 0; i < 4; i++) {
            float y = acc[i][j] * sc + sh;
            y = y > 0.f ? y : SLOPE * y;
            out[((img * 256 + oc) * 16 + oh[i]) * 16 + ow[i]] = y;
        }
    }
}

// =====================================================================
// conv3: h2[256,256,16,16] -> embeds g_data[256,4096] (feature = oc*64 + oh*8 + ow)
// grid(256). block 256 = 64 spatial x 4 oc-groups (oc tile = 64 = all).
// thread: 1 spatial x 16 oc. ic chunks of 8. static smem 26.6KB.
// =====================================================================
__global__ __launch_bounds__(256) void conv3_kernel(
    const float* __restrict__ in, const float* __restrict__ w,
    const float* __restrict__ bias, const float* __restrict__ g,
    const float* __restrict__ beta, const float* __restrict__ m,
    const float* __restrict__ v, float* __restrict__ out)
{
    __shared__ float in_s[8 * 256];     // 2048
    __shared__ float w_s[64 * 8 * 9];   // 4608

    int img = blockIdx.x;
    int tid = threadIdx.x;
    int sg = tid & 63, og = tid >> 6;
    int oh = sg >> 3, ow = sg & 7;

    float acc[16];
#pragma unroll
    for (int j = 0; j < 16; j++) acc[j] = 0.f;

    for (int icb = 0; icb < 256; icb += 8) {
        __syncthreads();
        const float* ip = in + (img * 256 + icb) * 256;
        for (int i = tid; i < 2048; i += 256) in_s[i] = ip[i];
        for (int i = tid; i < 4608; i += 256) {
            int ocl = i / 72, rem = i % 72;
            w_s[i] = w[ocl * 2304 + icb * 9 + rem];
        }
        __syncthreads();

#pragma unroll
        for (int ic = 0; ic < 8; ic++)
#pragma unroll
            for (int kh = 0; kh < 3; kh++)
#pragma unroll
                for (int kw = 0; kw < 3; kw++) {
                    int ih = 2 * oh - 1 + kh;
                    int iw = 2 * ow - 1 + kw;
                    float vv = (ih >= 0 && ih < 16 && iw >= 0 && iw < 16)
                                   ? in_s[ic * 256 + ih * 16 + iw] : 0.f;
#pragma unroll
                    for (int j = 0; j < 16; j++)
                        acc[j] = fmaf(vv, w_s[(og * 16 + j) * 72 + ic * 9 + kh * 3 + kw], acc[j]);
                }
    }

#pragma unroll
    for (int j = 0; j < 16; j++) {
        int oc = og * 16 + j;
        float sc = g[oc] / sqrtf(v[oc] + BN_EPS);
        float sh = beta[oc] - m[oc] * sc + bias[oc] * sc;
        float y = acc[j] * sc + sh;
        y = y > 0.f ? y : SLOPE * y;
        out[img * 4096 + oc * 64 + sg] = y;   // embed layout
    }
}

// =====================================================================
// row L2 normalize, in place. grid 256, block 256.
// =====================================================================
__global__ __launch_bounds__(256) void normalize_kernel(float* __restrict__ data)
{
    int row = blockIdx.x, tid = threadIdx.x;
    float* dr = data + row * 4096;
    float vals[16];
    float s = 0.f;
#pragma unroll
    for (int i = 0; i < 16; i++) {
        vals[i] = dr[tid + i * 256];
        s = fmaf(vals[i], vals[i], s);
    }
    __shared__ float sm[9];
    int lane = tid & 31, warp = tid >> 5;
#pragma unroll
    for (int off = 16; off > 0; off >>= 1) s += __shfl_down_sync(0xffffffffu, s, off);
    if (lane == 0) sm[warp] = s;
    __syncthreads();
    if (tid == 0) {
        float t = 0.f;
        for (int w = 0; w < 8; w++) t += sm[w];
        sm[8] = 1.f / sqrtf(t);
    }
    __syncthreads();
    float inv = sm[8];
#pragma unroll
    for (int i = 0; i < 16; i++) dr[tid + i * 256] = vals[i] * inv;
}

// =====================================================================
// copy mu0 -> muA
// =====================================================================
__global__ __launch_bounds__(256) void copy_kernel(const float* __restrict__ src, float* __restrict__ dst)
{
    int i = blockIdx.x * 256 + threadIdx.x;
    if (i < 16 * 4096) dst[i] = src[i];
}

// =====================================================================
// dist + softmax: r[row,k] = softmax_k(30 * data[row] . mu[k])
// grid 256 (row), block 256.
// =====================================================================
__global__ __launch_bounds__(256) void dist_softmax_kernel(
    const float* __restrict__ data, const float* __restrict__ mu, float* __restrict__ rout)
{
    int row = blockIdx.x, tid = threadIdx.x;
    const float* dr = data + row * 4096;
    float acc[16];
#pragma unroll
    for (int k = 0; k < 16; k++) acc[k] = 0.f;
#pragma unroll 4
    for (int i = 0; i < 16; i++) {
        int j = tid + i * 256;
        float dj = __ldg(dr + j);
#pragma unroll
        for (int k = 0; k < 16; k++) acc[k] = fmaf(dj, __ldg(mu + k * 4096 + j), acc[k]);
    }
    __shared__ float wsum[8][16];
    int lane = tid & 31, warp = tid >> 5;
#pragma unroll
    for (int k = 0; k < 16; k++) {
        float v = acc[k];
#pragma unroll
        for (int off = 16; off > 0; off >>= 1) v += __shfl_down_sync(0xffffffffu, v, off);
        if (lane == 0) wsum[warp][k] = v;
    }
    __syncthreads();
    if (tid == 0) {
        float d[16];
        float mx = -1e30f;
#pragma unroll
        for (int k = 0; k < 16; k++) {
            float s = 0.f;
            for (int w = 0; w < 8; w++) s += wsum[w][k];
            d[k] = CT * s;
            mx = fmaxf(mx, d[k]);
        }
        float sum = 0.f;
#pragma unroll
        for (int k = 0; k < 16; k++) { d[k] = expf(d[k] - mx); sum += d[k]; }
        float inv = 1.f / sum;
#pragma unroll
        for (int k = 0; k < 16; k++) rout[row * 16 + k] = d[k] * inv;
    }
}

// =====================================================================
// mu update: mu_out[k,f] = sum_n r[n,k] data[n,f] / sum_n r[n,k]
// grid 16 (feature chunks of 256), block 256 (one thread per feature).
// =====================================================================
__global__ __launch_bounds__(256) void update_mu_kernel(
    const float* __restrict__ r, const float* __restrict__ data, float* __restrict__ mu_out)
{
    __shared__ float rs[256 * 16];
    __shared__ float inv_cs[16];
    int tid = threadIdx.x;
    int f = blockIdx.x * 256 + tid;
    for (int i = tid; i < 4096; i += 256) rs[i] = r[i];
    __syncthreads();
    if (tid < 16) {
        float s = 0.f;
        for (int n = 0; n < 256; n++) s += rs[n * 16 + tid];
        inv_cs[tid] = 1.f / s;
    }
    __syncthreads();

    float acc[16];
#pragma unroll
    for (int k = 0; k < 16; k++) acc[k] = 0.f;
    for (int n = 0; n < 256; n++) {
        float d = __ldg(data + n * 4096 + f);
#pragma unroll
        for (int k = 0; k < 16; k++) acc[k] = fmaf(rs[n * 16 + k], d, acc[k]);
    }
#pragma unroll
    for (int k = 0; k < 16; k++) mu_out[k * 4096 + f] = acc[k] * inv_cs[k];
}

// =====================================================================
// host
// =====================================================================
extern "C" void kernel_launch(void* const* d_in, const int* in_sizes, int n_in,
                              void* d_out, int out_size)
{
    const float* x   = (const float*)d_in[0];
    const float* w1  = (const float*)d_in[1];
    const float* b1  = (const float*)d_in[2];
    const float* g1  = (const float*)d_in[3];
    const float* be1 = (const float*)d_in[4];
    const float* m1  = (const float*)d_in[5];
    const float* v1  = (const float*)d_in[6];
    const float* w2  = (const float*)d_in[7];
    const float* b2  = (const float*)d_in[8];
    const float* g2  = (const float*)d_in[9];
    const float* be2 = (const float*)d_in[10];
    const float* m2  = (const float*)d_in[11];
    const float* v2  = (const float*)d_in[12];
    const float* w3  = (const float*)d_in[13];
    const float* b3  = (const float*)d_in[14];
    const float* g3  = (const float*)d_in[15];
    const float* be3 = (const float*)d_in[16];
    const float* m3  = (const float*)d_in[17];
    const float* v3  = (const float*)d_in[18];
    const float* mu0 = (const float*)d_in[19];
    // d_in[20] = num_iter, fixed at 10 by the reference setup.

    float *h1, *h2, *data, *muA, *muB, *r;
    cudaGetSymbolAddress((void**)&h1, g_h1);
    cudaGetSymbolAddress((void**)&h2, g_h2);
    cudaGetSymbolAddress((void**)&data, g_data);
    cudaGetSymbolAddress((void**)&muA, g_muA);
    cudaGetSymbolAddress((void**)&muB, g_muB);
    cudaGetSymbolAddress((void**)&r, g_r);

    const int smem1 = (12288 + 432 + 32) * 4;   // 50.9 KB
    const int smem2 = (8192 + 4608) * 4;        // 51.2 KB
    cudaFuncSetAttribute(conv1_kernel, cudaFuncAttributeMaxDynamicSharedMemorySize, smem1);
    cudaFuncSetAttribute(conv2_kernel, cudaFuncAttributeMaxDynamicSharedMemorySize, smem2);

    conv1_kernel<<<dim3(256, 8), 256, smem1>>>(x, w1, b1, g1, be1, m1, v1, h1);
    conv2_kernel<<<dim3(256, 4), 256, smem2>>>(h1, w2, b2, g2, be2, m2, v2, h2);
    conv3_kernel<<<256, 256>>>(h2, w3, b3, g3, be3, m3, v3, data);
    normalize_kernel<<<256, 256>>>(data);
    copy_kernel<<<256, 256>>>(mu0, muA);

    // 11 mu updates total (10 in the first soft_kmeans + 1 in the second)
    for (int it = 0; it < 11; it++) {
        dist_softmax_kernel<<<256, 256>>>(data, muA, r);
        update_mu_kernel<<<16, 256>>>(r, data, muB);
        float* t = muA; muA = muB; muB = t;
    }
    // final r straight into output
    dist_softmax_kernel<<<256, 256>>>(data, muA, (float*)d_out);
}